// round 4
// baseline (speedup 1.0000x reference)
#include <cuda_runtime.h>
#include <math.h>

#define G      1024
#define GI     (G - 2)
#define B      4
#define N_TOT  (B * G * G)

#define TX 128
#define TY 32
#define SUW 136          // staged u/w tile width  (cols C0-4 .. C0+131)
#define SUH 36           // staged u/w tile height (rows R0-2 .. R0+33)
#define S1W 132          // s1 tile width (130 used, padded)
#define S1H 34           // s1 rows R0-1 .. R0+32
#define SMEM_FLOATS (2 * SUH * SUW + S1H * S1W)   // 14280 -> 57120 B

__device__ float g_w  [N_TOT];
__device__ float g_h  [N_TOT];   // 0.5 / y3   (0 on boundary)
__device__ float g_F  [N_TOT];   // f*H^2 / y3 (0 on boundary)
__device__ float g_u0 [N_TOT];
__device__ float g_u1 [N_TOT];

// ------------------------ precompute ------------------------
__global__ void k_w(const float4* __restrict__ prev, const float* __restrict__ mu) {
    int idx = blockIdx.x * blockDim.x + threadIdx.x;
    if (idx >= N_TOT / 4) return;
    float m = mu[0];
    float4 p = prev[idx];
    ((float4*)g_w)[idx] = make_float4(expf(m * p.x), expf(m * p.y),
                                      expf(m * p.z), expf(m * p.w));
}

__global__ void k_init(const float* __restrict__ pre) {
    int j = blockIdx.x * blockDim.x + threadIdx.x;
    int i = blockIdx.y;
    int b = blockIdx.z;
    if (j >= G) return;
    int idx = (b * G + i) * G + j;
    bool border = (i == 0 || i == G - 1 || j == 0 || j == G - 1);
    g_u0[idx] = border ? 0.0f : pre[(b * GI + (i - 1)) * GI + (j - 1)];
    if (border) g_u1[idx] = 0.0f;   // interior of u1 is overwritten by step 1
}

__global__ void k_coef(const float* __restrict__ f) {
    int j = blockIdx.x * blockDim.x + threadIdx.x;
    int i = blockIdx.y;
    int b = blockIdx.z;
    if (j >= G) return;
    int idx = (b * G + i) * G + j;
    if (i < 1 || i > G - 2 || j < 1 || j > G - 2) {
        g_h[idx] = 0.0f; g_F[idx] = 0.0f;
        return;
    }
    float wc = g_w[idx];
    float y3  = 0.5f * (g_w[idx - G] + g_w[idx + G] + g_w[idx - 1] + g_w[idx + 1]) + 2.0f * wc;
    float iy3 = 1.0f / y3;
    const float HH = (1.0f / 1023.0f) * (1.0f / 1023.0f);
    g_h[idx] = 0.5f * iy3;
    g_F[idx] = f[idx] * HH * iy3;
}

// ------------------------ single plain sweep (first step) ------------------------
__global__ void k_step(int parity) {
    int j0 = (blockIdx.x * blockDim.x + threadIdx.x) * 4;
    int i  = blockIdx.y * blockDim.y + threadIdx.y + 1;
    int b  = blockIdx.z;
    if (i > G - 2) return;
    int idx = (b * G + i) * G + j0;

    const float* __restrict__ u = parity ? g_u1 : g_u0;
    float4 uC4 = *(const float4*)(u + idx);
    float4 uN4 = *(const float4*)(u + idx - G);
    float4 uS4 = *(const float4*)(u + idx + G);
    float  uLl = u[idx - 1];
    float  uRr = u[idx + 4];
    float4 wC4 = *(const float4*)(g_w + idx);
    float4 wN4 = *(const float4*)(g_w + idx - G);
    float4 wS4 = *(const float4*)(g_w + idx + G);
    float  wLl = g_w[idx - 1];
    float  wRr = g_w[idx + 4];
    float4 h4 = *(const float4*)(g_h + idx);
    float4 F4 = *(const float4*)(g_F + idx);

    float uc[6] = { uLl, uC4.x, uC4.y, uC4.z, uC4.w, uRr };
    float wc[6] = { wLl, wC4.x, wC4.y, wC4.z, wC4.w, wRr };
    float un[4] = { uN4.x, uN4.y, uN4.z, uN4.w };
    float us[4] = { uS4.x, uS4.y, uS4.z, uS4.w };
    float wn[4] = { wN4.x, wN4.y, wN4.z, wN4.w };
    float ws[4] = { wS4.x, wS4.y, wS4.z, wS4.w };
    float hh[4] = { h4.x, h4.y, h4.z, h4.w };
    float ff[4] = { F4.x, F4.y, F4.z, F4.w };

    float r[4];
#pragma unroll
    for (int k = 0; k < 4; ++k) {
        float uW = uc[k], uE = uc[k + 2];
        float s = wc[k + 1] * (uW + uE + un[k] + us[k]);
        s = fmaf(wc[k],     uW,    s);
        s = fmaf(wc[k + 2], uE,    s);
        s = fmaf(wn[k],     un[k], s);
        s = fmaf(ws[k],     us[k], s);
        r[k] = fmaf(hh[k], s, ff[k]);
    }

    float* __restrict__ dst = parity ? g_u0 : g_u1;
    if (j0 == 0) {
        dst[idx + 1] = r[1]; dst[idx + 2] = r[2]; dst[idx + 3] = r[3];
    } else if (j0 == G - 4) {
        dst[idx] = r[0]; dst[idx + 1] = r[1]; dst[idx + 2] = r[2];
    } else {
        *(float4*)(dst + idx) = make_float4(r[0], r[1], r[2], r[3]);
    }
}

// ------------------------ fused 2-step smem-tile kernel ------------------------
// Block: 256 threads, output tile 128 cols x 32 rows.
// Phase 1: stage u, w (36 x 136) to smem (float4, guarded).
// Phase 2: s1 on 34 x 130 halo region -> smem (boundary cells auto-0 via h=F=0).
// Phase 3: step-2 on 32 x 128 from smem, 1 col/thread (conflict-free LDS).
template <bool FINAL>
__global__ void __launch_bounds__(256)
k_step2(int parity, float* __restrict__ out)
{
    extern __shared__ float sm[];
    float* su = sm;
    float* sw = sm + SUH * SUW;
    float* s1 = sm + 2 * SUH * SUW;

    int tid = threadIdx.x;
    int C0 = blockIdx.x * TX;
    int R0 = 1 + blockIdx.y * TY;
    int b  = blockIdx.z;

    const float* __restrict__ U  = (parity ? g_u1 : g_u0) + b * G * G;
    float* __restrict__       Dd = (parity ? g_u0 : g_u1) + b * G * G;
    const float* __restrict__ W  = g_w + b * G * G;
    const float* __restrict__ Hh = g_h + b * G * G;
    const float* __restrict__ Ff = g_F + b * G * G;

    // ---- phase 1: stage u, w ----
    for (int s = tid; s < SUH * 34; s += 256) {
        int lr = s / 34, q = s - lr * 34;
        int a = R0 - 2 + lr;
        int j = C0 - 4 + q * 4;
        float4 uv = make_float4(0.f, 0.f, 0.f, 0.f);
        float4 wv = uv;
        if ((unsigned)a < (unsigned)G && (unsigned)j < (unsigned)G) {
            uv = *(const float4*)(U + a * G + j);
            wv = *(const float4*)(W + a * G + j);
        }
        *(float4*)(su + lr * SUW + q * 4) = uv;
        *(float4*)(sw + lr * SUW + q * 4) = wv;
    }
    __syncthreads();

    // ---- phase 2: step-1 over 34 x 130 ----
    for (int e = tid; e < S1H * 130; e += 256) {
        int lr = e / 130, lc = e - lr * 130;
        int a = R0 - 1 + lr;
        int j = C0 - 1 + lc;
        float v = 0.0f;
        if ((unsigned)a < (unsigned)G && (unsigned)j < (unsigned)G) {
            int ur = lr + 1, uc = lc + 3;
            float uW = su[ur * SUW + uc - 1], uE = su[ur * SUW + uc + 1];
            float uN = su[(ur - 1) * SUW + uc], uS = su[(ur + 1) * SUW + uc];
            float wC = sw[ur * SUW + uc];
            float wW = sw[ur * SUW + uc - 1], wE = sw[ur * SUW + uc + 1];
            float wN = sw[(ur - 1) * SUW + uc], wS = sw[(ur + 1) * SUW + uc];
            float h  = Hh[a * G + j], Fv = Ff[a * G + j];
            float ss = wC * (uW + uE + uN + uS);
            ss = fmaf(wW, uW, ss); ss = fmaf(wE, uE, ss);
            ss = fmaf(wN, uN, ss); ss = fmaf(wS, uS, ss);
            v = fmaf(h, ss, Fv);
        }
        s1[lr * S1W + lc] = v;
    }
    __syncthreads();

    // ---- phase 3: step-2 over 32 x 128, 1 col/thread ----
    for (int t = tid; t < TY * TX; t += 256) {
        int lr  = t >> 7;          // 0..31
        int lc0 = t & 127;         // 0..127
        int i = R0 + lr;
        if (i > G - 2) continue;
        int j = C0 + lc0;

        float h  = Hh[i * G + j];
        float Fv = Ff[i * G + j];

        int s1r = lr + 1, lc = lc0 + 1;
        int wr  = lr + 2, wc_ = lc0 + 4;
        float uW = s1[s1r * S1W + lc - 1], uE = s1[s1r * S1W + lc + 1];
        float uN = s1[(s1r - 1) * S1W + lc], uS = s1[(s1r + 1) * S1W + lc];
        float wC = sw[wr * SUW + wc_];
        float wW = sw[wr * SUW + wc_ - 1], wE = sw[wr * SUW + wc_ + 1];
        float wN = sw[(wr - 1) * SUW + wc_], wS = sw[(wr + 1) * SUW + wc_];

        float ss = wC * (uW + uE + uN + uS);
        ss = fmaf(wW, uW, ss); ss = fmaf(wE, uE, ss);
        ss = fmaf(wN, uN, ss); ss = fmaf(wS, uS, ss);
        float r = fmaf(h, ss, Fv);

        if (FINAL) {
            if (j >= 1 && j <= G - 2)
                out[((long)b * GI + (i - 1)) * GI + (j - 1)] = r;
        } else {
            Dd[i * G + j] = r;
        }
    }
}

extern "C" void kernel_launch(void* const* d_in, const int* in_sizes, int n_in,
                              void* d_out, int out_size) {
    const float* pre  = (const float*)d_in[0];   // [B,1,1022,1022]
    const float* f    = (const float*)d_in[1];   // [B,1,1024,1024]
    const float* mu   = (const float*)d_in[2];   // [1]
    const float* prev = (const float*)d_in[3];   // [B,1,1024,1024]
    // d_in[4] = maxiter (fixed = 20 -> 21 total steps)
    float* out = (float*)d_out;

    static bool attr_done = false;
    if (!attr_done) {
        cudaFuncSetAttribute(k_step2<false>, cudaFuncAttributeMaxDynamicSharedMemorySize,
                             SMEM_FLOATS * 4);
        cudaFuncSetAttribute(k_step2<true>, cudaFuncAttributeMaxDynamicSharedMemorySize,
                             SMEM_FLOATS * 4);
        attr_done = true;
    }

    // precompute
    k_w<<<(N_TOT / 4 + 255) / 256, 256>>>((const float4*)prev, mu);
    dim3 blk(256, 1, 1);
    dim3 grd_full((G + 255) / 256, G, B);
    k_init<<<grd_full, blk>>>(pre);
    k_coef<<<grd_full, blk>>>(f);

    // step 1: plain sweep u0 -> u1
    dim3 sblk(32, 8, 1);
    dim3 sgrd(G / 128, (GI + 7) / 8, B);
    k_step<<<sgrd, sblk>>>(0);

    // steps 2..21: ten fused 2-step launches (smem tiles)
    dim3 tblk(256, 1, 1);
    dim3 tgrd(G / TX, (GI + TY - 1) / TY, B);    // 8 x 32 x 4 = 1024 blocks
    size_t smem = SMEM_FLOATS * 4;
    for (int k = 0; k < 9; ++k) {
        k_step2<false><<<tgrd, tblk, smem>>>((k & 1) ? 0 : 1, nullptr);
    }
    k_step2<true><<<tgrd, tblk, smem>>>(0, out);
}

// round 5
// speedup vs baseline: 1.0698x; 1.0698x over previous
#include <cuda_runtime.h>
#include <math.h>

#define G      1024
#define GI     (G - 2)
#define B      4
#define N_TOT  (B * G * G)

__device__ float g_w  [N_TOT];   // exp(mu * prev_pre)
__device__ float g_h  [N_TOT];   // 0.5 / y3   (0 on boundary)
__device__ float g_F  [N_TOT];   // f*H^2 / y3 (0 on boundary)
__device__ float g_u0 [N_TOT];
__device__ float g_u1 [N_TOT];

// ---------- fused precompute: w, h, F in one pass (neighbor w recomputed in-reg) ----------
__global__ void k_pre(const float* __restrict__ prev, const float* __restrict__ f,
                      const float* __restrict__ mu) {
    int j0 = (blockIdx.x * blockDim.x + threadIdx.x) * 4;   // 0..1020
    int i  = blockIdx.y;
    int b  = blockIdx.z;
    int base = (b * G + i) * G + j0;
    float m = mu[0];

    float4 pC = *(const float4*)(prev + base);
    float4 pN = (i > 0)     ? *(const float4*)(prev + base - G) : make_float4(0, 0, 0, 0);
    float4 pS = (i < G - 1) ? *(const float4*)(prev + base + G) : make_float4(0, 0, 0, 0);
    float  pL = (j0 > 0)       ? prev[base - 1] : 0.0f;
    float  pR = (j0 < G - 4)   ? prev[base + 4] : 0.0f;

    float wc[6] = { expf(m * pL), expf(m * pC.x), expf(m * pC.y),
                    expf(m * pC.z), expf(m * pC.w), expf(m * pR) };
    float wn[4] = { expf(m * pN.x), expf(m * pN.y), expf(m * pN.z), expf(m * pN.w) };
    float ws[4] = { expf(m * pS.x), expf(m * pS.y), expf(m * pS.z), expf(m * pS.w) };

    // write w (center 4)
    *(float4*)(g_w + base) = make_float4(wc[1], wc[2], wc[3], wc[4]);

    float4 fC = *(const float4*)(f + base);
    float ff[4] = { fC.x, fC.y, fC.z, fC.w };

    float h[4], Fo[4];
    bool rowIn = (i >= 1 && i <= G - 2);
    const float HH = (1.0f / 1023.0f) * (1.0f / 1023.0f);
#pragma unroll
    for (int k = 0; k < 4; ++k) {
        int j = j0 + k;
        bool in = rowIn && (j >= 1 && j <= G - 2);
        float y3  = 0.5f * (wn[k] + ws[k] + wc[k] + wc[k + 2]) + 2.0f * wc[k + 1];
        float iy3 = 1.0f / y3;
        h[k]  = in ? 0.5f * iy3       : 0.0f;
        Fo[k] = in ? ff[k] * HH * iy3 : 0.0f;
    }
    *(float4*)(g_h + base) = make_float4(h[0], h[1], h[2], h[3]);
    *(float4*)(g_F + base) = make_float4(Fo[0], Fo[1], Fo[2], Fo[3]);
}

// ---------- init u0 (interior = pre, border = 0), zero u1 border ----------
__global__ void k_init(const float* __restrict__ pre) {
    int j = blockIdx.x * blockDim.x + threadIdx.x;
    int i = blockIdx.y;
    int b = blockIdx.z;
    if (j >= G) return;
    int idx = (b * G + i) * G + j;
    bool border = (i == 0 || i == G - 1 || j == 0 || j == G - 1);
    g_u0[idx] = border ? 0.0f : pre[(b * GI + (i - 1)) * GI + (j - 1)];
    if (border) g_u1[idx] = 0.0f;
}

// ---------- one Jacobi sweep, 4 cols/thread, float4 ----------
template <bool FINAL>
__global__ void __launch_bounds__(512)
k_step(int parity, float* __restrict__ out) {
    int j0 = (blockIdx.x * blockDim.x + threadIdx.x) * 4;
    int i  = blockIdx.y * blockDim.y + threadIdx.y + 1;
    int b  = blockIdx.z;
    if (i > G - 2) return;
    int idx = (b * G + i) * G + j0;

    const float* __restrict__ u = parity ? g_u1 : g_u0;
    float4 uC4 = *(const float4*)(u + idx);
    float4 uN4 = *(const float4*)(u + idx - G);
    float4 uS4 = *(const float4*)(u + idx + G);
    float  uLl = u[idx - 1];
    float  uRr = u[idx + 4];
    float4 wC4 = *(const float4*)(g_w + idx);
    float4 wN4 = *(const float4*)(g_w + idx - G);
    float4 wS4 = *(const float4*)(g_w + idx + G);
    float  wLl = g_w[idx - 1];
    float  wRr = g_w[idx + 4];
    float4 h4 = *(const float4*)(g_h + idx);
    float4 F4 = *(const float4*)(g_F + idx);

    float uc[6] = { uLl, uC4.x, uC4.y, uC4.z, uC4.w, uRr };
    float wc[6] = { wLl, wC4.x, wC4.y, wC4.z, wC4.w, wRr };
    float un[4] = { uN4.x, uN4.y, uN4.z, uN4.w };
    float us[4] = { uS4.x, uS4.y, uS4.z, uS4.w };
    float wn[4] = { wN4.x, wN4.y, wN4.z, wN4.w };
    float ws[4] = { wS4.x, wS4.y, wS4.z, wS4.w };
    float hh[4] = { h4.x, h4.y, h4.z, h4.w };
    float ff[4] = { F4.x, F4.y, F4.z, F4.w };

    float r[4];
#pragma unroll
    for (int k = 0; k < 4; ++k) {
        float uW = uc[k], uE = uc[k + 2];
        float s = wc[k + 1] * (uW + uE + un[k] + us[k]);
        s = fmaf(wc[k],     uW,    s);
        s = fmaf(wc[k + 2], uE,    s);
        s = fmaf(wn[k],     un[k], s);
        s = fmaf(ws[k],     us[k], s);
        r[k] = fmaf(hh[k], s, ff[k]);
    }

    if (FINAL) {
        long obase = ((long)b * GI + (i - 1)) * GI;
#pragma unroll
        for (int k = 0; k < 4; ++k) {
            int j = j0 + k;
            if (j >= 1 && j <= G - 2)
                out[obase + (j - 1)] = r[k];
        }
    } else {
        float* __restrict__ dst = parity ? g_u0 : g_u1;
        if (j0 == 0) {
            dst[idx + 1] = r[1]; dst[idx + 2] = r[2]; dst[idx + 3] = r[3];
        } else if (j0 == G - 4) {
            dst[idx] = r[0]; dst[idx + 1] = r[1]; dst[idx + 2] = r[2];
        } else {
            *(float4*)(dst + idx) = make_float4(r[0], r[1], r[2], r[3]);
        }
    }
}

extern "C" void kernel_launch(void* const* d_in, const int* in_sizes, int n_in,
                              void* d_out, int out_size) {
    const float* pre  = (const float*)d_in[0];   // [B,1,1022,1022]
    const float* f    = (const float*)d_in[1];   // [B,1,1024,1024]
    const float* mu   = (const float*)d_in[2];   // [1]
    const float* prev = (const float*)d_in[3];   // [B,1,1024,1024]
    // d_in[4] = maxiter (fixed = 20 -> 21 total steps)
    float* out = (float*)d_out;

    // precompute: w,h,F in one pass; u0/u1 init in parallel (independent)
    dim3 pblk(64, 1, 1);                 // 64 threads x 4 cols = 256 cols
    dim3 pgrd(G / 256, G, B);
    k_pre<<<pgrd, pblk>>>(prev, f, mu);

    dim3 iblk(256, 1, 1);
    dim3 igrd((G + 255) / 256, G, B);
    k_init<<<igrd, iblk>>>(pre);

    // 21 Jacobi sweeps, ping-pong; last writes d_out
    dim3 sblk(32, 16, 1);                // 128 cols x 16 rows per block
    dim3 sgrd(G / 128, (GI + 15) / 16, B);
    for (int t = 0; t < 20; ++t) {
        k_step<false><<<sgrd, sblk>>>(t & 1, nullptr);
    }
    k_step<true><<<sgrd, sblk>>>(20 & 1, out);
}